// round 9
// baseline (speedup 1.0000x reference)
#include <cuda_runtime.h>
#include <stdint.h>

#define RNODES 256
#define LUT_WORDS 8192            // 2^18 / 32
#define NSTEP 512
#define NSAMP 512
#define NIN 32
#define NOUT 10

// Hybrid split:
//  - SMEM 2-bit combo groups: sg=0..17 -> bits {2sg, 2sg+1} (k=0..35),
//    sg=18 -> {252,253}, sg=19 -> {254,255}. 4 combos incl. zero row.
#define NSG 20
#define TAB2_N (NSG * 4 * 128)          // 10240 u32 = 40 KB
//  - L2 12-bit groups: g=0..17 covering bits 36+12g .. 47+12g (k=36..251)
#define NG12 18
#define TAB12_ROWS (NG12 * 4096)        // 73728 rows x 128 u32-pairs = 37.7 MB
// 6-bit half tables for building tab12: h=0..35, k = 36 + 6h + j
#define NH6 36
#define TAB6_ROWS (NH6 * 64)

// Static device scratch (allocation-free rule).
__device__ uint32_t g_lutbits[RNODES * LUT_WORDS];   // 8 MB bit-packed LUT (L2)
__device__ uint16_t g_tab6[TAB6_ROWS * RNODES];      // 1.2 MB half tables
__device__ uint32_t g_tab12[TAB12_ROWS * 128];       // 37.7 MB pair table (L2)
__device__ uint32_t g_tab2[TAB2_N];                  // 40 KB SMEM-staging table
__device__ uint32_t g_xpack[NSAMP * NSTEP];          // per (m,s): 32 input bits
__device__ int      g_inv[RNODES];                   // node -> input slot, or -1
__device__ int      g_init[RNODES];                  // initial state bits
__device__ int      g_mode;                          // bool enc: 0=i32 1=u8 2=f32

__device__ __forceinline__ int read_bool(const void* p, long i, int mode) {
    if (mode == 0) return ((const int*)p)[i] != 0;
    if (mode == 1) return ((const unsigned char*)p)[i] != 0;
    return ((const float*)p)[i] != 0.0f;
}

__global__ void detect_kernel(const uint32_t* __restrict__ xw) {
    int lane = threadIdx.x;
    if (blockIdx.x || lane >= 32) return;
    int isf = 0, big = 0;
    for (int i = 0; i < 32; i++) {
        uint32_t v = xw[i * 32 + lane];
        if (v == 0x3f800000u) isf = 1;
        if (v > 1u) big = 1;
    }
    unsigned af = __ballot_sync(0xffffffffu, isf);
    unsigned ab = __ballot_sync(0xffffffffu, big);
    if (lane == 0) g_mode = af ? 2 : (ab ? 1 : 0);
}

// Warp-ballot LUT pack: fully coalesced 1 GB stream (DRAM-bound).
__global__ void pack_lut_kernel(const int* __restrict__ lut) {
    int gwarp = (blockIdx.x * blockDim.x + threadIdx.x) >> 5;
    int lane  = threadIdx.x & 31;
    const int* base = lut + (size_t)gwarp * 1024;
    uint32_t mine = 0;
#pragma unroll
    for (int w = 0; w < 32; w++) {
        int v = base[w * 32 + lane];
        unsigned m = __ballot_sync(0xffffffffu, v & 1);
        if (lane == w) mine = m;
    }
    g_lutbits[(size_t)gwarp * 32 + lane] = mine;
}

__global__ void pack_x_kernel(const void* __restrict__ x) {
    int gwarp = (blockIdx.x * blockDim.x + threadIdx.x) >> 5;
    int lane  = threadIdx.x & 31;
    int mode  = g_mode;
    long base = (long)gwarp * 1024;
    uint32_t mine = 0;
#pragma unroll
    for (int w = 0; w < 32; w++) {
        int v = read_bool(x, base + w * 32 + lane, mode);
        unsigned m = __ballot_sync(0xffffffffu, v);
        if (lane == w) mine = m;
    }
    g_xpack[gwarp * 32 + lane] = mine;
}

// misc (inv/init) + 6-bit half tables (k=36..251) + 2-bit SMEM staging table
#define SEC_MISC RNODES
#define SEC_T6   (TAB6_ROWS * RNODES)
#define SEC_T2   TAB2_N
__global__ void prep_small_kernel(const int* __restrict__ input_nodes,
                                  const void* __restrict__ init_res,
                                  const void* __restrict__ W,
                                  const int* __restrict__ primes) {
    int i = blockIdx.x * blockDim.x + threadIdx.x;
    int mode = g_mode;
    if (i < SEC_MISC) {
        int inv = -1;
#pragma unroll
        for (int q = 0; q < NIN; q++)
            if (input_nodes[q] == i) inv = q;
        g_inv[i] = inv;
        g_init[i] = read_bool(init_res, i, mode);
    }
    i -= SEC_MISC;
    if (i >= 0 && i < SEC_T6) {
        // tab6 entry (h, c, node): sum over combo bits j, k = 36 + 6h + j
        int node = i & 255;
        int c    = (i >> 8) & 63;
        int h    = i >> 14;
        uint32_t sum = 0;
#pragma unroll
        for (int j = 0; j < 6; j++) {
            int k = 36 + 6 * h + j;
            if (c & (1 << j)) {
                if (read_bool(W, (long)node * RNODES + k, mode))
                    sum += (uint32_t)primes[k];
            }
        }
        g_tab6[i] = (uint16_t)sum;
        return;
    }
    i -= SEC_T6;
    if (i >= 0 && i < SEC_T2) {
        // tab2 entry (sg, c, t): u16 pair {node t, node t+128}
        int t  = i & 127;
        int c  = (i >> 7) & 3;
        int sg = i >> 9;
        int k0 = (sg < 18) ? 2 * sg : 252 + 2 * (sg - 18);
        uint32_t lo = 0, hi = 0;
#pragma unroll
        for (int j = 0; j < 2; j++) {
            if (c & (1 << j)) {
                int k = k0 + j;
                uint32_t p = (uint32_t)primes[k];
                if (read_bool(W, (long)t * RNODES + k, mode))         lo += p;
                if (read_bool(W, (long)(t + 128) * RNODES + k, mode)) hi += p;
            }
        }
        g_tab2[i] = lo | (hi << 16);
    }
}

// Build paired 12-bit table from 6-bit halves (write-bound, 37.7 MB).
__global__ void prep2_kernel() {
    int i = blockIdx.x * blockDim.x + threadIdx.x;
    if (i >= TAB12_ROWS * 128) return;
    int t   = i & 127;
    int row = i >> 7;
    int g   = row >> 12;
    int c   = row & 4095;
    int r0  = (2 * g) * 64 + (c & 63);
    int r1  = (2 * g + 1) * 64 + (c >> 6);
    uint32_t lo = (uint32_t)g_tab6[r0 * RNODES + t]
                + (uint32_t)g_tab6[r1 * RNODES + t];
    uint32_t hi = (uint32_t)g_tab6[r0 * RNODES + t + 128]
                + (uint32_t)g_tab6[r1 * RNODES + t + 128];
    g_tab12[i] = lo | (hi << 16);
}

// 512 CTAs x 128 threads. CTA = one sample; thread t owns nodes t and t+128.
// Hybrid sums: 20 SMEM 2-bit groups (one u16-pair acc, max ~9.1K) +
// 18 L2 12-bit groups (u16-pair acc spilled every 3 groups).
__global__ void __launch_bounds__(128, 4)
reservoir_kernel(const float* __restrict__ roW,
                 const float* __restrict__ rob,
                 float* __restrict__ out) {
    __shared__ uint32_t sh_tab2[TAB2_N];   // 40 KB
    __shared__ uint32_t sh_xw[NSTEP];      // 2 KB
    __shared__ uint32_t sh_r[16];          // 2 bufs * 8 mask words
    __shared__ float    sh_bits[RNODES];

    const int t    = threadIdx.x;       // 0..127
    const int w    = t >> 5;
    const int lane = t & 31;
    const int sid  = blockIdx.x;

    for (int i = t; i < TAB2_N; i += 128)
        sh_tab2[i] = g_tab2[i];
    for (int i = t; i < NSTEP; i += 128)
        sh_xw[i] = g_xpack[sid * NSTEP + i];

    const int inv0 = g_inv[t];
    const int inv1 = g_inv[t + 128];
    unsigned b0 = (unsigned)g_init[t];
    unsigned b1 = (unsigned)g_init[t + 128];

    __syncthreads();

    for (int s = 0; s < NSTEP; s++) {
        // 1) input override (before the matvec, as in the reference)
        uint32_t xw = sh_xw[s];
        unsigned a0 = (inv0 >= 0) ? ((xw >> inv0) & 1u) : b0;
        unsigned a1 = (inv1 >= 0) ? ((xw >> inv1) & 1u) : b1;

        // 2) state bitmask words: warp w -> words w and w+4
        unsigned m0 = __ballot_sync(0xffffffffu, a0);
        unsigned m1 = __ballot_sync(0xffffffffu, a1);
        uint32_t* rb = sh_r + (s & 1) * 8;
        if (lane == 0) { rb[w] = m0; rb[w + 4] = m1; }
        __syncthreads();

        uint4 ra  = *(const uint4*)(rb);
        uint4 rb4 = *(const uint4*)(rb + 4);
        uint32_t wv[8] = {ra.x, ra.y, ra.z, ra.w, rb4.x, rb4.y, rb4.z, rb4.w};

        // 3a) SMEM 2-bit groups: bits 0..35 (sg 0..17) + bits 252..255 (sg 18,19)
        uint32_t accS = 0;   // packed u16 pair; max ~9.1K, no overflow
#pragma unroll
        for (int sg = 0; sg < 18; sg++) {
            uint32_t c = (wv[sg >> 4] >> (2 * (sg & 15))) & 3u;
            accS = __vadd2(accS, sh_tab2[((sg << 2) + c) * 128 + t]);
        }
        {
            uint32_t c18 = (wv[7] >> 28) & 3u;
            uint32_t c19 = (wv[7] >> 30) & 3u;
            accS = __vadd2(accS, sh_tab2[((18 << 2) + c18) * 128 + t]);
            accS = __vadd2(accS, sh_tab2[((19 << 2) + c19) * 128 + t]);
        }
        uint32_t i0 = accS & 0xFFFFu;
        uint32_t i1 = accS >> 16;

        // 3b) L2 12-bit groups: bits 36..251, 18 independent coalesced LDG.32
#pragma unroll
        for (int trip = 0; trip < 6; trip++) {
            uint32_t acc = 0;   // packed u16; 3 groups max < 58.3K
#pragma unroll
            for (int j = 0; j < 3; j++) {
                int g  = trip * 3 + j;
                int bp = 36 + 12 * g;
                int wi = bp >> 5, sh = bp & 31;
                uint32_t c = __funnelshift_r(wv[wi], wv[(wi + 1) & 7], sh) & 0xFFFu;
                acc = __vadd2(acc, g_tab12[((uint32_t)g << 19) + (c << 7) + t]);
            }
            i0 += acc & 0xFFFFu;
            i1 += acc >> 16;
        }

        // 4) bit-packed LUT gather (8 MB, L2-resident)
        uint32_t w0 = g_lutbits[((uint32_t)t << 13)         + (i0 >> 5)];
        uint32_t w1 = g_lutbits[((uint32_t)(t + 128) << 13) + (i1 >> 5)];
        b0 = (w0 >> (i0 & 31u)) & 1u;
        b1 = (w1 >> (i1 & 31u)) & 1u;
    }

    // Readout: out[m, o] = sum_j rf[m,j] * roW[o,j] + rob[o]
    sh_bits[t]       = (float)b0;
    sh_bits[t + 128] = (float)b1;
    __syncthreads();

    if (t < NOUT) {
        float acc = rob[t];
        const float* wrow = roW + t * RNODES;
#pragma unroll 8
        for (int j = 0; j < RNODES; j++)
            acc += sh_bits[j] * wrow[j];
        out[sid * NOUT + t] = acc;
    }
}

extern "C" void kernel_launch(void* const* d_in, const int* in_sizes, int n_in,
                              void* d_out, int out_size) {
    const void* x       = d_in[0];                   // bool [512,512,4,8] (dtype-detected)
    const int*  innod   = (const int*)d_in[1];       // int32 [32]
    const int*  lut     = (const int*)d_in[2];       // int32 [256, 262144]
    const void* W       = d_in[3];                   // bool [256,256]
    const int*  primes  = (const int*)d_in[4];       // int32 [256]
    const void* initres = d_in[5];                   // bool [256]
    const float* roW    = (const float*)d_in[6];     // f32 [10,256]
    const float* rob    = (const float*)d_in[7];     // f32 [10]
    float* out = (float*)d_out;                      // f32 [512,10]

    detect_kernel<<<1, 32>>>((const uint32_t*)x);
    pack_lut_kernel<<<8192, 256>>>(lut);             // 1 GB stream, DRAM-bound
    pack_x_kernel<<<1024, 256>>>(x);
    prep_small_kernel<<<(SEC_MISC + SEC_T6 + SEC_T2 + 255) / 256, 256>>>(
        innod, initres, W, primes);
    prep2_kernel<<<(TAB12_ROWS * 128 + 255) / 256, 256>>>();
    reservoir_kernel<<<NSAMP, 128>>>(roW, rob, out);
}

// round 10
// speedup vs baseline: 1.5900x; 1.5900x over previous
#include <cuda_runtime.h>
#include <stdint.h>

#define RNODES 256
#define LUT_WORDS 8192            // 2^18 / 32
#define NSTEP 512
#define NSAMP 512
#define NIN 32
#define NOUT 10

// 6-bit half-groups: 43 (last covers k=252..255; k>=256 guarded to zero)
#define NH6 43
#define TAB6_ROWS (NH6 * 64)
// 12-bit groups: 21 full (g=0..20, k=0..251) + one 4-bit tail (k=252..255)
#define NG12 21
#define TAB12_TAIL (NG12 * 4096)        // 86016
#define TAB12_ROWS (TAB12_TAIL + 16)    // 86032 rows x 128 u32-pairs = 44 MB

// Static device scratch (allocation-free rule).
__device__ uint32_t g_lutbits[RNODES * LUT_WORDS];   // 8 MB bit-packed LUT (L2)
__device__ uint16_t g_tab6[TAB6_ROWS * RNODES];      // 1.4 MB half tables
__device__ uint32_t g_tab12[TAB12_ROWS * 128];       // 44 MB pair table (L2)
__device__ uint32_t g_xpack[NSAMP * NSTEP];          // per (m,s): 32 input bits
__device__ int      g_inv[RNODES];                   // node -> input slot, or -1
__device__ int      g_init[RNODES];                  // initial state bits
__device__ int      g_mode;                          // bool enc: 0=i32 1=u8 2=f32

__device__ __forceinline__ int read_bool(const void* p, long i, int mode) {
    if (mode == 0) return ((const int*)p)[i] != 0;
    if (mode == 1) return ((const unsigned char*)p)[i] != 0;
    return ((const float*)p)[i] != 0.0f;
}

__global__ void detect_kernel(const uint32_t* __restrict__ xw) {
    int lane = threadIdx.x;
    if (blockIdx.x || lane >= 32) return;
    int isf = 0, big = 0;
    for (int i = 0; i < 32; i++) {
        uint32_t v = xw[i * 32 + lane];
        if (v == 0x3f800000u) isf = 1;
        if (v > 1u) big = 1;
    }
    unsigned af = __ballot_sync(0xffffffffu, isf);
    unsigned ab = __ballot_sync(0xffffffffu, big);
    if (lane == 0) g_mode = af ? 2 : (ab ? 1 : 0);
}

// Warp-ballot LUT pack: fully coalesced 1 GB stream (DRAM-bound).
__global__ void pack_lut_kernel(const int* __restrict__ lut) {
    int gwarp = (blockIdx.x * blockDim.x + threadIdx.x) >> 5;
    int lane  = threadIdx.x & 31;
    const int* base = lut + (size_t)gwarp * 1024;
    uint32_t mine = 0;
#pragma unroll
    for (int w = 0; w < 32; w++) {
        int v = base[w * 32 + lane];
        unsigned m = __ballot_sync(0xffffffffu, v & 1);
        if (lane == w) mine = m;
    }
    g_lutbits[(size_t)gwarp * 32 + lane] = mine;
}

__global__ void pack_x_kernel(const void* __restrict__ x) {
    int gwarp = (blockIdx.x * blockDim.x + threadIdx.x) >> 5;
    int lane  = threadIdx.x & 31;
    int mode  = g_mode;
    long base = (long)gwarp * 1024;
    uint32_t mine = 0;
#pragma unroll
    for (int w = 0; w < 32; w++) {
        int v = read_bool(x, base + w * 32 + lane, mode);
        unsigned m = __ballot_sync(0xffffffffu, v);
        if (lane == w) mine = m;
    }
    g_xpack[gwarp * 32 + lane] = mine;
}

// misc (inv/init) + 6-bit half tables
#define SEC_MISC RNODES
#define SEC_T6   (TAB6_ROWS * RNODES)
__global__ void prep_small_kernel(const int* __restrict__ input_nodes,
                                  const void* __restrict__ init_res,
                                  const void* __restrict__ W,
                                  const int* __restrict__ primes) {
    int i = blockIdx.x * blockDim.x + threadIdx.x;
    int mode = g_mode;
    if (i < SEC_MISC) {
        int inv = -1;
#pragma unroll
        for (int q = 0; q < NIN; q++)
            if (input_nodes[q] == i) inv = q;
        g_inv[i] = inv;
        g_init[i] = read_bool(init_res, i, mode);
    }
    i -= SEC_MISC;
    if (i < 0 || i >= SEC_T6) return;
    // tab6 entry (h, c, node): sum over combo bits j of half-group h (k=6h+j)
    int node = i & 255;
    int c    = (i >> 8) & 63;
    int h    = i >> 14;
    uint32_t sum = 0;
#pragma unroll
    for (int j = 0; j < 6; j++) {
        int k = 6 * h + j;
        if ((c & (1 << j)) && k < RNODES) {
            if (read_bool(W, (long)node * RNODES + k, mode))
                sum += (uint32_t)primes[k];
        }
    }
    g_tab6[i] = (uint16_t)sum;
}

// Build paired 12-bit table from 6-bit halves (write-bound, 44 MB).
// Entry (row, t): u16 pair {node t, node t+128}.
__global__ void prep2_kernel() {
    int i = blockIdx.x * blockDim.x + threadIdx.x;
    if (i >= TAB12_ROWS * 128) return;
    int t   = i & 127;
    int row = i >> 7;
    uint32_t lo, hi;
    if (row < TAB12_TAIL) {
        int g  = row >> 12;
        int c  = row & 4095;
        int r0 = (2 * g) * 64 + (c & 63);
        int r1 = (2 * g + 1) * 64 + (c >> 6);
        lo = (uint32_t)g_tab6[r0 * RNODES + t]
           + (uint32_t)g_tab6[r1 * RNODES + t];
        hi = (uint32_t)g_tab6[r0 * RNODES + t + 128]
           + (uint32_t)g_tab6[r1 * RNODES + t + 128];
    } else {
        int r = 42 * 64 + (row - TAB12_TAIL);     // k = 252..255
        lo = g_tab6[r * RNODES + t];
        hi = g_tab6[r * RNODES + t + 128];
    }
    g_tab12[i] = lo | (hi << 16);
}

// 512 CTAs x 128 threads. CTA = one sample; thread t owns nodes t and t+128.
// All 22 table loads are front-batched into registers (max MLP), then the
// packed-u16 add tree runs (spill every 3 groups; 3 * 19428 < 65536).
__global__ void __launch_bounds__(128, 4)
reservoir_kernel(const float* __restrict__ roW,
                 const float* __restrict__ rob,
                 float* __restrict__ out) {
    __shared__ uint32_t sh_xw[NSTEP];
    __shared__ uint32_t sh_r[16];       // 2 bufs * 8 mask words
    __shared__ float    sh_bits[RNODES];

    const int t    = threadIdx.x;       // 0..127
    const int w    = t >> 5;
    const int lane = t & 31;
    const int sid  = blockIdx.x;

    for (int i = t; i < NSTEP; i += 128)
        sh_xw[i] = g_xpack[sid * NSTEP + i];

    const int inv0 = g_inv[t];
    const int inv1 = g_inv[t + 128];
    unsigned b0 = (unsigned)g_init[t];
    unsigned b1 = (unsigned)g_init[t + 128];

    __syncthreads();

    for (int s = 0; s < NSTEP; s++) {
        // 1) input override (before the matvec, as in the reference)
        uint32_t xw = sh_xw[s];
        unsigned a0 = (inv0 >= 0) ? ((xw >> inv0) & 1u) : b0;
        unsigned a1 = (inv1 >= 0) ? ((xw >> inv1) & 1u) : b1;

        // 2) state bitmask words: warp w -> words w and w+4
        unsigned m0 = __ballot_sync(0xffffffffu, a0);
        unsigned m1 = __ballot_sync(0xffffffffu, a1);
        uint32_t* rb = sh_r + (s & 1) * 8;
        if (lane == 0) { rb[w] = m0; rb[w + 4] = m1; }
        __syncthreads();

        uint4 ra  = *(const uint4*)(rb);
        uint4 rb4 = *(const uint4*)(rb + 4);
        uint32_t wv[8] = {ra.x, ra.y, ra.z, ra.w, rb4.x, rb4.y, rb4.z, rb4.w};

        // 3) 12-bit-group pair sums: compute ALL combo addresses, then issue
        //    22 back-to-back LDG.32 (front-batched MLP), then accumulate.
        uint32_t e[NG12 + 1];
#pragma unroll
        for (int g = 0; g < NG12; g++) {
            int bp = 12 * g;
            int wi = bp >> 5, sh = bp & 31;
            uint32_t c = __funnelshift_r(wv[wi], wv[(wi + 1) & 7], sh) & 0xFFFu;
            e[g] = __ldcg(&g_tab12[((uint32_t)g << 19) + (c << 7) + t]);
        }
        e[NG12] = __ldcg(&g_tab12[((uint32_t)TAB12_TAIL << 7)
                                  + ((wv[7] >> 28) << 7) + t]);

        uint32_t i0 = 0, i1 = 0;
#pragma unroll
        for (int trip = 0; trip < 7; trip++) {
            uint32_t acc = __vadd2(__vadd2(e[3 * trip], e[3 * trip + 1]),
                                   e[3 * trip + 2]);
            i0 += acc & 0xFFFFu;
            i1 += acc >> 16;
        }
        i0 += e[NG12] & 0xFFFFu;
        i1 += e[NG12] >> 16;

        // 4) bit-packed LUT gather (8 MB, L2-resident)
        uint32_t w0 = __ldcg(&g_lutbits[((uint32_t)t << 13)         + (i0 >> 5)]);
        uint32_t w1 = __ldcg(&g_lutbits[((uint32_t)(t + 128) << 13) + (i1 >> 5)]);
        b0 = (w0 >> (i0 & 31u)) & 1u;
        b1 = (w1 >> (i1 & 31u)) & 1u;
    }

    // Readout: out[m, o] = sum_j rf[m,j] * roW[o,j] + rob[o]
    sh_bits[t]       = (float)b0;
    sh_bits[t + 128] = (float)b1;
    __syncthreads();

    if (t < NOUT) {
        float acc = rob[t];
        const float* wrow = roW + t * RNODES;
#pragma unroll 8
        for (int j = 0; j < RNODES; j++)
            acc += sh_bits[j] * wrow[j];
        out[sid * NOUT + t] = acc;
    }
}

extern "C" void kernel_launch(void* const* d_in, const int* in_sizes, int n_in,
                              void* d_out, int out_size) {
    const void* x       = d_in[0];                   // bool [512,512,4,8] (dtype-detected)
    const int*  innod   = (const int*)d_in[1];       // int32 [32]
    const int*  lut     = (const int*)d_in[2];       // int32 [256, 262144]
    const void* W       = d_in[3];                   // bool [256,256]
    const int*  primes  = (const int*)d_in[4];       // int32 [256]
    const void* initres = d_in[5];                   // bool [256]
    const float* roW    = (const float*)d_in[6];     // f32 [10,256]
    const float* rob    = (const float*)d_in[7];     // f32 [10]
    float* out = (float*)d_out;                      // f32 [512,10]

    detect_kernel<<<1, 32>>>((const uint32_t*)x);
    pack_lut_kernel<<<8192, 256>>>(lut);             // 1 GB stream, DRAM-bound
    pack_x_kernel<<<1024, 256>>>(x);
    prep_small_kernel<<<(SEC_MISC + SEC_T6 + 255) / 256, 256>>>(innod, initres, W, primes);
    prep2_kernel<<<(TAB12_ROWS * 128 + 255) / 256, 256>>>();
    reservoir_kernel<<<NSAMP, 128>>>(roW, rob, out);
}